// round 8
// baseline (speedup 1.0000x reference)
#include <cuda_runtime.h>
#include <cuda_bf16.h>
#include <cstdint>

#define NROWS   131072
#define DDIM    256
#define NW      256
#define NB      8
#define LW      32
#define TAUQ    5.0f

#define Z_ELEMS   (NROWS * DDIM)
#define IDX_ELEMS (NROWS * NB)
#define C_ELEMS   (NW * DDIM)

#define QMARGIN 4e-4f

// ---- SMEM layout (bytes) ----
#define OFF_SC2   0        // 256 f32
#define OFF_SN5   1024     // 256 f32  (-5*c2)
#define OFF_SXF   2048     // 128 x 34 f32 exact x rows
#define OFF_SCF   19456    // 256 x 33 f32 exact C rows
#define OFF_RQ    53248    // 128 x 16 f32 candidate q
#define OFF_RI    61440    // 128 x 16 i32 candidate w
#define OFF_B1HI  69632    // 256 x 40 bf16 (Cb hi, [w][k])
#define OFF_B1LO  90112
#define OFF_B2HI  110592   // 32 x 264 bf16 (Cb^T hi, [j][w])
#define OFF_B2LO  127488
#define SMEM_TOTAL 144384
#define B1S 40
#define B2S 264
#define XFS 34
#define CFS 33

__device__ __forceinline__ uint32_t cvta_s(const void* p) {
    uint32_t a;
    asm("{ .reg .u64 t; cvta.to.shared.u64 t, %1; cvt.u32.u64 %0, t; }" : "=r"(a) : "l"(p));
    return a;
}
// pack two f32 -> bf16x2 (lo in low half)
__device__ __forceinline__ uint32_t packbf(float lo, float hi) {
    uint32_t r;
    asm("cvt.rn.bf16x2.f32 %0, %1, %2;" : "=r"(r) : "f"(hi), "f"(lo));
    return r;
}
__device__ __forceinline__ void ldsm4(uint32_t a, uint32_t& r0, uint32_t& r1, uint32_t& r2, uint32_t& r3) {
    asm volatile("ldmatrix.sync.aligned.m8n8.x4.shared.b16 {%0,%1,%2,%3}, [%4];"
                 : "=r"(r0), "=r"(r1), "=r"(r2), "=r"(r3) : "r"(a));
}
__device__ __forceinline__ void mma16816(float* d, const uint32_t* a, uint32_t b0, uint32_t b1) {
    asm volatile("mma.sync.aligned.m16n8k16.row.col.f32.bf16.bf16.f32 "
                 "{%0,%1,%2,%3}, {%4,%5,%6,%7}, {%8,%9}, {%0,%1,%2,%3};"
                 : "+f"(d[0]), "+f"(d[1]), "+f"(d[2]), "+f"(d[3])
                 : "r"(a[0]), "r"(a[1]), "r"(a[2]), "r"(a[3]), "r"(b0), "r"(b1));
}

// Exact tree sum of squares (reference bit chain — frozen)
__device__ __forceinline__ float tree_sumsq32(const float* v) {
    float s[32];
    #pragma unroll
    for (int i = 0; i < 32; ++i) s[i] = __fmul_rn(v[i], v[i]);
    #pragma unroll
    for (int st = 16; st >= 1; st >>= 1) {
        #pragma unroll
        for (int i = 0; i < st; ++i) s[i] = __fadd_rn(s[i], s[i + st]);
    }
    return s[0];
}

#define INS4(qv, wv, Q, I) do { \
    if ((qv) > Q[3]) { \
        if ((qv) > Q[0])      { Q[3]=Q[2];I[3]=I[2]; Q[2]=Q[1];I[2]=I[1]; Q[1]=Q[0];I[1]=I[0]; Q[0]=(qv);I[0]=(wv); } \
        else if ((qv) > Q[1]) { Q[3]=Q[2];I[3]=I[2]; Q[2]=Q[1];I[2]=I[1]; Q[1]=(qv);I[1]=(wv); } \
        else if ((qv) > Q[2]) { Q[3]=Q[2];I[3]=I[2]; Q[2]=(qv);I[2]=(wv); } \
        else                  { Q[3]=(qv);I[3]=(wv); } \
    } } while (0)

__global__ void __launch_bounds__(256, 1)
softpq_mma(const float* __restrict__ x, const float* __restrict__ C, float* __restrict__ out)
{
    extern __shared__ char sm[];
    float* sc2 = (float*)(sm + OFF_SC2);
    float* sn5 = (float*)(sm + OFF_SN5);
    float* sXf = (float*)(sm + OFF_SXF);
    float* sCf = (float*)(sm + OFF_SCF);
    float* rqA = (float*)(sm + OFF_RQ);
    int*   riA = (int*)(sm + OFF_RI);
    __nv_bfloat16* b1h = (__nv_bfloat16*)(sm + OFF_B1HI);
    __nv_bfloat16* b1l = (__nv_bfloat16*)(sm + OFF_B1LO);
    __nv_bfloat16* b2h = (__nv_bfloat16*)(sm + OFF_B2HI);
    __nv_bfloat16* b2l = (__nv_bfloat16*)(sm + OFF_B2LO);

    const uint32_t sb1h = cvta_s(sm + OFF_B1HI), sb1l = cvta_s(sm + OFF_B1LO);
    const uint32_t sb2h = cvta_s(sm + OFF_B2HI), sb2l = cvta_s(sm + OFF_B2LO);

    const int tid = threadIdx.x, wid = tid >> 5, lid = tid & 31;
    const int g = lid >> 2, tig = lid & 3;
    const int rowbase = blockIdx.x * 128;

    // ldmatrix per-lane row addressing helpers
    const int lq = lid >> 3, lr = lid & 7;      // quadrant, row-in-8x8

    for (int book = 0; book < NB; ++book) {
        // ================= Phase A: stage smem =================
        {
            const int w = tid;
            float cv[32];
            const float4* cs = (const float4*)(C + (size_t)w * DDIM + book * LW);
            #pragma unroll
            for (int j = 0; j < 8; ++j) {
                float4 v = cs[j];
                cv[4*j+0] = v.x; cv[4*j+1] = v.y; cv[4*j+2] = v.z; cv[4*j+3] = v.w;
            }
            float c2 = tree_sumsq32(cv);
            sc2[w] = c2;
            sn5[w] = -TAUQ * c2;
            #pragma unroll
            for (int k = 0; k < 32; ++k) {
                float v = cv[k];
                sCf[w * CFS + k] = v;
                __nv_bfloat16 h = __float2bfloat16(v);
                __nv_bfloat16 l = __float2bfloat16(v - __bfloat162float(h));
                b1h[w * B1S + k] = h;  b1l[w * B1S + k] = l;
                b2h[k * B2S + w] = h;  b2l[k * B2S + w] = l;
            }
            // X staging: 2 threads per row
            const int row = tid >> 1, hf = tid & 1;
            const float4* xs = (const float4*)(x + (size_t)(rowbase + row) * DDIM + book * LW + hf * 16);
            #pragma unroll
            for (int j = 0; j < 4; ++j) {
                float4 v = xs[j];
                float* d = &sXf[row * XFS + hf * 16 + 4 * j];
                d[0] = v.x; d[1] = v.y; d[2] = v.z; d[3] = v.w;
            }
        }
        __syncthreads();

        // ================= Build A1 fragments (X, split bf16) =================
        uint32_t a1h[2][4], a1l[2][4];
        {
            const int r0 = wid * 16 + g;
            #pragma unroll
            for (int c = 0; c < 2; ++c) {
                const int d0 = c * 16 + 2 * tig;
                #pragma unroll
                for (int rr = 0; rr < 2; ++rr) {
                    const float* xr = &sXf[(r0 + rr * 8) * XFS];
                    float v0 = xr[d0], v1 = xr[d0+1], v8 = xr[d0+8], v9 = xr[d0+9];
                    __nv_bfloat16 h0 = __float2bfloat16(v0), h1 = __float2bfloat16(v1);
                    __nv_bfloat16 h8 = __float2bfloat16(v8), h9 = __float2bfloat16(v9);
                    float l0 = v0 - __bfloat162float(h0), l1 = v1 - __bfloat162float(h1);
                    float l8 = v8 - __bfloat162float(h8), l9 = v9 - __bfloat162float(h9);
                    a1h[c][rr]     = packbf(__bfloat162float(h0), __bfloat162float(h1));
                    a1h[c][2 + rr] = packbf(__bfloat162float(h8), __bfloat162float(h9));
                    a1l[c][rr]     = packbf(l0, l1);
                    a1l[c][2 + rr] = packbf(l8, l9);
                }
            }
        }

        float d2[4][4];
        #pragma unroll
        for (int t = 0; t < 4; ++t)
            #pragma unroll
            for (int e = 0; e < 4; ++e) d2[t][e] = 0.f;

        float tq0[4] = {-3.4e38f, -3.4e38f, -3.4e38f, -3.4e38f};
        float tq1[4] = {-3.4e38f, -3.4e38f, -3.4e38f, -3.4e38f};
        int   ti0[4] = {-1, -1, -1, -1}, ti1[4] = {-1, -1, -1, -1};
        float ss0 = 0.f, ss1 = 0.f;

        // ================= Main loop: 16 codeword chunks =================
        #pragma unroll 1
        for (int i = 0; i < 16; ++i) {
            // --- GEMM1 B fragments (Cb^T), hi/lo, chunks k0/k1 ---
            uint32_t bh[8], bl[8];
            {
                uint32_t base = (uint32_t)((16 * i + (lq >> 1) * 8 + lr) * (B1S * 2) + (lq & 1) * 16);
                ldsm4(sb1h + base,      bh[0], bh[1], bh[2], bh[3]);
                ldsm4(sb1h + base + 32, bh[4], bh[5], bh[6], bh[7]);
                ldsm4(sb1l + base,      bl[0], bl[1], bl[2], bl[3]);
                ldsm4(sb1l + base + 32, bl[4], bl[5], bl[6], bl[7]);
            }
            float dt0[4] = {0.f, 0.f, 0.f, 0.f}, dt1[4] = {0.f, 0.f, 0.f, 0.f};
            // 3 split passes x 2 k-chunks, two n-tiles (t0: regs 0,1 / t1: regs 2,3)
            mma16816(dt0, a1h[0], bh[0], bh[1]);  mma16816(dt0, a1h[1], bh[4], bh[5]);
            mma16816(dt0, a1h[0], bl[0], bl[1]);  mma16816(dt0, a1h[1], bl[4], bl[5]);
            mma16816(dt0, a1l[0], bh[0], bh[1]);  mma16816(dt0, a1l[1], bh[4], bh[5]);
            mma16816(dt1, a1h[0], bh[2], bh[3]);  mma16816(dt1, a1h[1], bh[6], bh[7]);
            mma16816(dt1, a1h[0], bl[2], bl[3]);  mma16816(dt1, a1h[1], bl[6], bl[7]);
            mma16816(dt1, a1l[0], bh[2], bh[3]);  mma16816(dt1, a1l[1], bh[6], bh[7]);

            // --- epilogue: q, top4, exp, split P ---
            const int w0 = 16 * i + 2 * tig;
            float2 pa = *(const float2*)&sn5[w0];
            float2 pb = *(const float2*)&sn5[w0 + 8];
            float qa0 = fmaf(10.f, dt0[0], pa.x), qa1 = fmaf(10.f, dt0[1], pa.y);
            float qb0 = fmaf(10.f, dt1[0], pb.x), qb1 = fmaf(10.f, dt1[1], pb.y);
            float qc0 = fmaf(10.f, dt0[2], pa.x), qc1 = fmaf(10.f, dt0[3], pa.y);
            float qd0 = fmaf(10.f, dt1[2], pb.x), qd1 = fmaf(10.f, dt1[3], pb.y);
            INS4(qa0, w0,     tq0, ti0); INS4(qa1, w0 + 1, tq0, ti0);
            INS4(qb0, w0 + 8, tq0, ti0); INS4(qb1, w0 + 9, tq0, ti0);
            INS4(qc0, w0,     tq1, ti1); INS4(qc1, w0 + 1, tq1, ti1);
            INS4(qd0, w0 + 8, tq1, ti1); INS4(qd1, w0 + 9, tq1, ti1);
            float pa0 = __expf(qa0), pa1 = __expf(qa1), pb0 = __expf(qb0), pb1 = __expf(qb1);
            float pc0 = __expf(qc0), pc1 = __expf(qc1), pd0 = __expf(qd0), pd1 = __expf(qd1);
            ss0 += (pa0 + pa1) + (pb0 + pb1);
            ss1 += (pc0 + pc1) + (pd0 + pd1);

            uint32_t a2h[4], a2l[4];
            {
                __nv_bfloat16 h;
                float r0a, r0b, r1a, r1b, r2a, r2b, r3a, r3b;
                h = __float2bfloat16(pa0); r0a = pa0 - __bfloat162float(h); float ha0 = __bfloat162float(h);
                h = __float2bfloat16(pa1); r0b = pa1 - __bfloat162float(h); float ha1 = __bfloat162float(h);
                h = __float2bfloat16(pc0); r1a = pc0 - __bfloat162float(h); float hc0 = __bfloat162float(h);
                h = __float2bfloat16(pc1); r1b = pc1 - __bfloat162float(h); float hc1 = __bfloat162float(h);
                h = __float2bfloat16(pb0); r2a = pb0 - __bfloat162float(h); float hb0 = __bfloat162float(h);
                h = __float2bfloat16(pb1); r2b = pb1 - __bfloat162float(h); float hb1 = __bfloat162float(h);
                h = __float2bfloat16(pd0); r3a = pd0 - __bfloat162float(h); float hd0 = __bfloat162float(h);
                h = __float2bfloat16(pd1); r3b = pd1 - __bfloat162float(h); float hd1 = __bfloat162float(h);
                a2h[0] = packbf(ha0, ha1); a2h[1] = packbf(hc0, hc1);
                a2h[2] = packbf(hb0, hb1); a2h[3] = packbf(hd0, hd1);
                a2l[0] = packbf(r0a, r0b); a2l[1] = packbf(r1a, r1b);
                a2l[2] = packbf(r2a, r2b); a2l[3] = packbf(r3a, r3b);
            }

            // --- GEMM2 B fragments (Cb, [j][w]) and online accumulation ---
            uint32_t ch[8], cl[8];
            {
                uint32_t o1 = (uint32_t)(((lq >> 1) * 8 + lr) * (B2S * 2) + (16 * i + (lq & 1) * 8) * 2);
                uint32_t o2 = o1 + (uint32_t)(16 * (B2S * 2));
                ldsm4(sb2h + o1, ch[0], ch[1], ch[2], ch[3]);
                ldsm4(sb2h + o2, ch[4], ch[5], ch[6], ch[7]);
                ldsm4(sb2l + o1, cl[0], cl[1], cl[2], cl[3]);
                ldsm4(sb2l + o2, cl[4], cl[5], cl[6], cl[7]);
            }
            #pragma unroll
            for (int t = 0; t < 4; ++t) {
                mma16816(d2[t], a2h, ch[2*t], ch[2*t+1]);
                mma16816(d2[t], a2h, cl[2*t], cl[2*t+1]);
                mma16816(d2[t], a2l, ch[2*t], ch[2*t+1]);
            }
        }

        // ================= reduce ssum across the quad, store Z =================
        ss0 += __shfl_xor_sync(0xffffffffu, ss0, 1);
        ss0 += __shfl_xor_sync(0xffffffffu, ss0, 2);
        ss1 += __shfl_xor_sync(0xffffffffu, ss1, 1);
        ss1 += __shfl_xor_sync(0xffffffffu, ss1, 2);
        const float inv0 = 1.f / ss0, inv1 = 1.f / ss1;

        {
            const int r0 = rowbase + wid * 16 + g;
            #pragma unroll
            for (int t = 0; t < 4; ++t) {
                size_t o = (size_t)r0 * DDIM + book * LW + 8 * t + 2 * tig;
                float2 v0 = make_float2(d2[t][0] * inv0, d2[t][1] * inv0);
                float2 v1 = make_float2(d2[t][2] * inv1, d2[t][3] * inv1);
                *(float2*)&out[o] = v0;
                *(float2*)&out[o + 8 * DDIM] = v1;
            }
        }

        // ================= stage candidates, recheck, idx =================
        {
            const int lr0 = wid * 16 + g;
            #pragma unroll
            for (int c = 0; c < 4; ++c) {
                rqA[lr0 * 16 + tig * 4 + c] = tq0[c];
                riA[lr0 * 16 + tig * 4 + c] = ti0[c];
                rqA[(lr0 + 8) * 16 + tig * 4 + c] = tq1[c];
                riA[(lr0 + 8) * 16 + tig * 4 + c] = ti1[c];
            }
        }
        __syncthreads();

        if (tid < 128) {
            const int row = tid;
            float qs[16]; int is[16];
            #pragma unroll
            for (int c = 0; c < 16; ++c) { qs[c] = rqA[row * 16 + c]; is[c] = riA[row * 16 + c]; }
            float qmax = qs[0];
            #pragma unroll
            for (int c = 1; c < 16; ++c) qmax = fmaxf(qmax, qs[c]);

            float xv[32];
            #pragma unroll
            for (int k = 0; k < 32; ++k) xv[k] = sXf[row * XFS + k];
            const float X2 = tree_sumsq32(xv);

            float bestKey = -3.4e38f; int bestW = NW;
            #pragma unroll 1
            for (int c = 0; c < 16; ++c) {
                int w = is[c];
                if (w < 0 || qs[c] < qmax - QMARGIN) continue;
                const float* cw = sCf + w * CFS;
                float de = 0.f;
                #pragma unroll
                for (int k = 0; k < 32; ++k) de = __fmaf_rn(xv[k], cw[k], de);
                float t    = __fadd_rn(X2, sc2[w]);
                float dist = __fmaf_rn(-2.f, de, t);
                float key  = __fmul_rn(-TAUQ, dist);
                if (key > bestKey || (key == bestKey && w < bestW)) { bestKey = key; bestW = w; }
            }
            out[(size_t)Z_ELEMS + (size_t)(rowbase + row) * NB + book] = (float)bestW;
        }
        __syncthreads();
    }
}

__global__ void copy_c_kernel(const float* __restrict__ C, float* __restrict__ out)
{
    int i = blockIdx.x * blockDim.x + threadIdx.x;
    if (i < C_ELEMS) out[(size_t)Z_ELEMS + IDX_ELEMS + i] = C[i];
}

extern "C" void kernel_launch(void* const* d_in, const int* in_sizes, int n_in,
                              void* d_out, int out_size)
{
    const float* x = (const float*)d_in[0];
    const float* C = (const float*)d_in[1];
    float* out = (float*)d_out;

    cudaFuncSetAttribute(softpq_mma, cudaFuncAttributeMaxDynamicSharedMemorySize, SMEM_TOTAL);
    softpq_mma<<<NROWS / 128, 256, SMEM_TOTAL>>>(x, C, out);
    copy_c_kernel<<<(C_ELEMS + 255) / 256, 256>>>(C, out);
}

// round 9
// speedup vs baseline: 1.9807x; 1.9807x over previous
#include <cuda_runtime.h>
#include <cuda_bf16.h>
#include <cstdint>

#define NROWS   131072
#define DDIM    256
#define NW      256
#define NB      8
#define LW      32
#define TAUQ    5.0f

#define Z_ELEMS   (NROWS * DDIM)
#define IDX_ELEMS (NROWS * NB)
#define C_ELEMS   (NW * DDIM)

#define QMARGIN 4e-4f
#define RPC     256          // rows per CTA
#define THREADS 512

#define XFS 34
#define CFS 33
#define B1S 40               // bf16 row stride (80B): conflict-free ldmatrix
#define B2S 264              // bf16 row stride (528B): conflict-free ldmatrix

// ---- SMEM layout (bytes) ----
#define OFF_SC2 0
#define OFF_SN5 1024
#define OFF_SXF 2048                     // 256 x 34 f32 = 34816
#define OFF_SCF (OFF_SXF + 34816)        // 256 x 33 f32 = 33792
#define OFF_RQ  (OFF_SCF + 33792)        // 256 x 8 f32  = 8192
#define OFF_RI  (OFF_RQ + 8192)          // 256 x 8 i32  = 8192
#define OFF_B1H (OFF_RI + 8192)          // 256 x 40 bf16 = 20480
#define OFF_B1L (OFF_B1H + 20480)
#define OFF_B2H (OFF_B1L + 20480)        // 32 x 264 bf16 = 16896
#define OFF_B2L (OFF_B2H + 16896)
#define SMEM_TOTAL (OFF_B2L + 16896)     // 161792

__device__ __forceinline__ uint32_t cvta_s(const void* p) {
    uint32_t a;
    asm("{ .reg .u64 t; cvta.to.shared.u64 t, %1; cvt.u32.u64 %0, t; }" : "=r"(a) : "l"(p));
    return a;
}
__device__ __forceinline__ uint32_t packbf(float lo, float hi) {
    uint32_t r;
    asm("cvt.rn.bf16x2.f32 %0, %1, %2;" : "=r"(r) : "f"(hi), "f"(lo));
    return r;
}
__device__ __forceinline__ void ldsm4(uint32_t a, uint32_t& r0, uint32_t& r1, uint32_t& r2, uint32_t& r3) {
    asm volatile("ldmatrix.sync.aligned.m8n8.x4.shared.b16 {%0,%1,%2,%3}, [%4];"
                 : "=r"(r0), "=r"(r1), "=r"(r2), "=r"(r3) : "r"(a));
}
__device__ __forceinline__ void mma16816(float* d, const uint32_t* a, uint32_t b0, uint32_t b1) {
    asm volatile("mma.sync.aligned.m16n8k16.row.col.f32.bf16.bf16.f32 "
                 "{%0,%1,%2,%3}, {%4,%5,%6,%7}, {%8,%9}, {%0,%1,%2,%3};"
                 : "+f"(d[0]), "+f"(d[1]), "+f"(d[2]), "+f"(d[3])
                 : "r"(a[0]), "r"(a[1]), "r"(a[2]), "r"(a[3]), "r"(b0), "r"(b1));
}

// Exact tree sum of squares (reference bit chain — frozen)
__device__ __forceinline__ float tree_sumsq32(const float* v) {
    float s[32];
    #pragma unroll
    for (int i = 0; i < 32; ++i) s[i] = __fmul_rn(v[i], v[i]);
    #pragma unroll
    for (int st = 16; st >= 1; st >>= 1) {
        #pragma unroll
        for (int i = 0; i < st; ++i) s[i] = __fadd_rn(s[i], s[i + st]);
    }
    return s[0];
}

#define INS2(qv, wv, Q, I) do { \
    if ((qv) > Q[1]) { \
        if ((qv) > Q[0]) { Q[1]=Q[0]; I[1]=I[0]; Q[0]=(qv); I[0]=(wv); } \
        else             { Q[1]=(qv); I[1]=(wv); } \
    } } while (0)

__global__ void __launch_bounds__(THREADS, 1)
softpq_mma(const float* __restrict__ x, const float* __restrict__ C, float* __restrict__ out)
{
    extern __shared__ char sm[];
    float* sc2 = (float*)(sm + OFF_SC2);
    float* sn5 = (float*)(sm + OFF_SN5);
    float* sXf = (float*)(sm + OFF_SXF);
    float* sCf = (float*)(sm + OFF_SCF);
    float* rqA = (float*)(sm + OFF_RQ);
    int*   riA = (int*)(sm + OFF_RI);
    __nv_bfloat16* b1h = (__nv_bfloat16*)(sm + OFF_B1H);
    __nv_bfloat16* b1l = (__nv_bfloat16*)(sm + OFF_B1L);
    __nv_bfloat16* b2h = (__nv_bfloat16*)(sm + OFF_B2H);
    __nv_bfloat16* b2l = (__nv_bfloat16*)(sm + OFF_B2L);

    const uint32_t sb1h = cvta_s(sm + OFF_B1H), sb1l = cvta_s(sm + OFF_B1L);
    const uint32_t sb2h = cvta_s(sm + OFF_B2H), sb2l = cvta_s(sm + OFF_B2L);

    const int tid = threadIdx.x, wid = tid >> 5, lid = tid & 31;
    const int g = lid >> 2, tig = lid & 3;
    const int lq = lid >> 3, lr = lid & 7;
    const int rowbase = blockIdx.x * RPC;

    #pragma unroll 1
    for (int book = 0; book < NB; ++book) {
        // ================= Phase A: stage smem (split across warps) =========
        if (tid < 256) {
            const int w = tid;
            float cv[32];
            const float4* cs = (const float4*)(C + (size_t)w * DDIM + book * LW);
            #pragma unroll
            for (int j = 0; j < 8; ++j) {
                float4 v = cs[j];
                cv[4*j+0] = v.x; cv[4*j+1] = v.y; cv[4*j+2] = v.z; cv[4*j+3] = v.w;
            }
            float c2 = tree_sumsq32(cv);
            sc2[w] = c2;
            sn5[w] = -TAUQ * c2;
            #pragma unroll
            for (int k = 0; k < 32; ++k) {
                float v = cv[k];
                sCf[w * CFS + k] = v;
                __nv_bfloat16 h = __float2bfloat16(v);
                __nv_bfloat16 l = __float2bfloat16(v - __bfloat162float(h));
                b1h[w * B1S + k] = h;  b1l[w * B1S + k] = l;
                b2h[k * B2S + w] = h;  b2l[k * B2S + w] = l;
            }
        } else {
            const int row = tid - 256;
            const float4* xs = (const float4*)(x + (size_t)(rowbase + row) * DDIM + book * LW);
            #pragma unroll
            for (int j = 0; j < 8; ++j) {
                float4 v = xs[j];
                float* d = &sXf[row * XFS + 4 * j];
                d[0] = v.x; d[1] = v.y; d[2] = v.z; d[3] = v.w;
            }
        }
        __syncthreads();

        // ================= Build A1 fragments (X, split bf16) ===============
        uint32_t a1h[2][4], a1l[2][4];
        {
            const int r0 = wid * 16 + g;
            #pragma unroll
            for (int c = 0; c < 2; ++c) {
                const int d0 = c * 16 + 2 * tig;
                #pragma unroll
                for (int rr = 0; rr < 2; ++rr) {
                    const float* xr = &sXf[(r0 + rr * 8) * XFS];
                    float v0 = xr[d0], v1 = xr[d0+1], v8 = xr[d0+8], v9 = xr[d0+9];
                    __nv_bfloat16 h0 = __float2bfloat16(v0), h1 = __float2bfloat16(v1);
                    __nv_bfloat16 h8 = __float2bfloat16(v8), h9 = __float2bfloat16(v9);
                    float l0 = v0 - __bfloat162float(h0), l1 = v1 - __bfloat162float(h1);
                    float l8 = v8 - __bfloat162float(h8), l9 = v9 - __bfloat162float(h9);
                    a1h[c][rr]     = packbf(__bfloat162float(h0), __bfloat162float(h1));
                    a1h[c][2 + rr] = packbf(__bfloat162float(h8), __bfloat162float(h9));
                    a1l[c][rr]     = packbf(l0, l1);
                    a1l[c][2 + rr] = packbf(l8, l9);
                }
            }
        }

        float d2[4][4];
        #pragma unroll
        for (int t = 0; t < 4; ++t)
            #pragma unroll
            for (int e = 0; e < 4; ++e) d2[t][e] = 0.f;

        float tq0[2] = {-3.4e38f, -3.4e38f}, tq1[2] = {-3.4e38f, -3.4e38f};
        int   ti0[2] = {-1, -1},             ti1[2] = {-1, -1};
        float ss0 = 0.f, ss1 = 0.f;

        // ================= Main loop: 16 codeword chunks ====================
        #pragma unroll 1
        for (int i = 0; i < 16; ++i) {
            float dt0[4] = {0.f, 0.f, 0.f, 0.f}, dt1[4] = {0.f, 0.f, 0.f, 0.f};
            #pragma unroll
            for (int kc = 0; kc < 2; ++kc) {
                uint32_t b4h[4], b4l[4];
                uint32_t base = (uint32_t)((16 * i + (lq >> 1) * 8 + lr) * (B1S * 2)
                                           + (lq & 1) * 16 + kc * 32);
                ldsm4(sb1h + base, b4h[0], b4h[1], b4h[2], b4h[3]);
                ldsm4(sb1l + base, b4l[0], b4l[1], b4l[2], b4l[3]);
                mma16816(dt0, a1h[kc], b4h[0], b4h[1]);
                mma16816(dt0, a1h[kc], b4l[0], b4l[1]);
                mma16816(dt0, a1l[kc], b4h[0], b4h[1]);
                mma16816(dt1, a1h[kc], b4h[2], b4h[3]);
                mma16816(dt1, a1h[kc], b4l[2], b4l[3]);
                mma16816(dt1, a1l[kc], b4h[2], b4h[3]);
            }

            // --- epilogue: q, top2, exp, split P ---
            const int w0 = 16 * i + 2 * tig;
            float2 pa = *(const float2*)&sn5[w0];
            float2 pb = *(const float2*)&sn5[w0 + 8];
            float qa0 = fmaf(10.f, dt0[0], pa.x), qa1 = fmaf(10.f, dt0[1], pa.y);
            float qb0 = fmaf(10.f, dt1[0], pb.x), qb1 = fmaf(10.f, dt1[1], pb.y);
            float qc0 = fmaf(10.f, dt0[2], pa.x), qc1 = fmaf(10.f, dt0[3], pa.y);
            float qd0 = fmaf(10.f, dt1[2], pb.x), qd1 = fmaf(10.f, dt1[3], pb.y);
            INS2(qa0, w0,     tq0, ti0); INS2(qa1, w0 + 1, tq0, ti0);
            INS2(qb0, w0 + 8, tq0, ti0); INS2(qb1, w0 + 9, tq0, ti0);
            INS2(qc0, w0,     tq1, ti1); INS2(qc1, w0 + 1, tq1, ti1);
            INS2(qd0, w0 + 8, tq1, ti1); INS2(qd1, w0 + 9, tq1, ti1);
            float pa0 = __expf(qa0), pa1 = __expf(qa1), pb0 = __expf(qb0), pb1 = __expf(qb1);
            float pc0 = __expf(qc0), pc1 = __expf(qc1), pd0 = __expf(qd0), pd1 = __expf(qd1);
            ss0 += (pa0 + pa1) + (pb0 + pb1);
            ss1 += (pc0 + pc1) + (pd0 + pd1);

            uint32_t a2h[4], a2l[4];
            {
                __nv_bfloat16 h;
                h = __float2bfloat16(pa0); float r0a = pa0 - __bfloat162float(h); float ha0 = __bfloat162float(h);
                h = __float2bfloat16(pa1); float r0b = pa1 - __bfloat162float(h); float ha1 = __bfloat162float(h);
                h = __float2bfloat16(pc0); float r1a = pc0 - __bfloat162float(h); float hc0 = __bfloat162float(h);
                h = __float2bfloat16(pc1); float r1b = pc1 - __bfloat162float(h); float hc1 = __bfloat162float(h);
                h = __float2bfloat16(pb0); float r2a = pb0 - __bfloat162float(h); float hb0 = __bfloat162float(h);
                h = __float2bfloat16(pb1); float r2b = pb1 - __bfloat162float(h); float hb1 = __bfloat162float(h);
                h = __float2bfloat16(pd0); float r3a = pd0 - __bfloat162float(h); float hd0 = __bfloat162float(h);
                h = __float2bfloat16(pd1); float r3b = pd1 - __bfloat162float(h); float hd1 = __bfloat162float(h);
                a2h[0] = packbf(ha0, ha1); a2h[1] = packbf(hc0, hc1);
                a2h[2] = packbf(hb0, hb1); a2h[3] = packbf(hd0, hd1);
                a2l[0] = packbf(r0a, r0b); a2l[1] = packbf(r1a, r1b);
                a2l[2] = packbf(r2a, r2b); a2l[3] = packbf(r3a, r3b);
            }

            // --- GEMM2 online accumulation ---
            #pragma unroll
            for (int hf2 = 0; hf2 < 2; ++hf2) {
                uint32_t c4h[4], c4l[4];
                uint32_t o = (uint32_t)((hf2 * 16 + (lq >> 1) * 8 + lr) * (B2S * 2)
                                        + (16 * i + (lq & 1) * 8) * 2);
                ldsm4(sb2h + o, c4h[0], c4h[1], c4h[2], c4h[3]);
                ldsm4(sb2l + o, c4l[0], c4l[1], c4l[2], c4l[3]);
                #pragma unroll
                for (int t2 = 0; t2 < 2; ++t2) {
                    float* dd = d2[hf2 * 2 + t2];
                    mma16816(dd, a2h, c4h[2*t2], c4h[2*t2+1]);
                    mma16816(dd, a2h, c4l[2*t2], c4l[2*t2+1]);
                    mma16816(dd, a2l, c4h[2*t2], c4h[2*t2+1]);
                }
            }
        }

        // ================= reduce ssum across quad, store Z =================
        ss0 += __shfl_xor_sync(0xffffffffu, ss0, 1);
        ss0 += __shfl_xor_sync(0xffffffffu, ss0, 2);
        ss1 += __shfl_xor_sync(0xffffffffu, ss1, 1);
        ss1 += __shfl_xor_sync(0xffffffffu, ss1, 2);
        const float inv0 = 1.f / ss0, inv1 = 1.f / ss1;

        {
            const int r0 = rowbase + wid * 16 + g;
            #pragma unroll
            for (int t = 0; t < 4; ++t) {
                size_t o = (size_t)r0 * DDIM + book * LW + 8 * t + 2 * tig;
                *(float2*)&out[o]            = make_float2(d2[t][0] * inv0, d2[t][1] * inv0);
                *(float2*)&out[o + 8 * DDIM] = make_float2(d2[t][2] * inv1, d2[t][3] * inv1);
            }
        }

        // ================= stage candidates, recheck, idx ===================
        {
            const int lr0 = wid * 16 + g;
            #pragma unroll
            for (int c = 0; c < 2; ++c) {
                rqA[lr0 * 8 + tig * 2 + c] = tq0[c];
                riA[lr0 * 8 + tig * 2 + c] = ti0[c];
                rqA[(lr0 + 8) * 8 + tig * 2 + c] = tq1[c];
                riA[(lr0 + 8) * 8 + tig * 2 + c] = ti1[c];
            }
        }
        __syncthreads();

        if (tid < 256) {
            const int row = tid;
            float qs[8]; int is[8];
            #pragma unroll
            for (int c = 0; c < 8; ++c) { qs[c] = rqA[row * 8 + c]; is[c] = riA[row * 8 + c]; }
            float qmax = qs[0];
            #pragma unroll
            for (int c = 1; c < 8; ++c) qmax = fmaxf(qmax, qs[c]);

            float xv[32];
            #pragma unroll
            for (int k = 0; k < 32; ++k) xv[k] = sXf[row * XFS + k];
            const float X2 = tree_sumsq32(xv);

            float bestKey = -3.4e38f; int bestW = NW;
            #pragma unroll 1
            for (int c = 0; c < 8; ++c) {
                int w = is[c];
                if (w < 0 || qs[c] < qmax - QMARGIN) continue;
                const float* cw = sCf + w * CFS;
                float de = 0.f;
                #pragma unroll
                for (int k = 0; k < 32; ++k) de = __fmaf_rn(xv[k], cw[k], de);
                float t    = __fadd_rn(X2, sc2[w]);
                float dist = __fmaf_rn(-2.f, de, t);
                float key  = __fmul_rn(-TAUQ, dist);
                if (key > bestKey || (key == bestKey && w < bestW)) { bestKey = key; bestW = w; }
            }
            out[(size_t)Z_ELEMS + (size_t)(rowbase + row) * NB + book] = (float)bestW;
        }
        __syncthreads();
    }
}

__global__ void copy_c_kernel(const float* __restrict__ C, float* __restrict__ out)
{
    int i = blockIdx.x * blockDim.x + threadIdx.x;
    if (i < C_ELEMS) out[(size_t)Z_ELEMS + IDX_ELEMS + i] = C[i];
}

extern "C" void kernel_launch(void* const* d_in, const int* in_sizes, int n_in,
                              void* d_out, int out_size)
{
    const float* x = (const float*)d_in[0];
    const float* C = (const float*)d_in[1];
    float* out = (float*)d_out;

    cudaFuncSetAttribute(softpq_mma, cudaFuncAttributeMaxDynamicSharedMemorySize, SMEM_TOTAL);
    // copy_c first so ncu's skip-count lands on the main kernel
    copy_c_kernel<<<(C_ELEMS + 255) / 256, 256>>>(C, out);
    softpq_mma<<<NROWS / RPC, THREADS, SMEM_TOTAL>>>(x, C, out);
}

// round 10
// speedup vs baseline: 2.3065x; 1.1645x over previous
#include <cuda_runtime.h>
#include <cuda_bf16.h>
#include <cuda_fp16.h>
#include <cstdint>

#define NROWS   131072
#define DDIM    256
#define NW      256
#define NB      8
#define LW      32
#define TAUQ    5.0f

#define Z_ELEMS   (NROWS * DDIM)
#define IDX_ELEMS (NROWS * NB)
#define C_ELEMS   (NW * DDIM)

#define QMARGIN 4e-4f
#define RPC     256
#define THREADS 512

#define XFS 34
#define CFS 33
#define B1S 40               // bf16 row stride (80B): conflict-free ldmatrix
#define B2S 264              // fp16 row stride (528B): conflict-free ldmatrix

// ---- SMEM layout (bytes) ----
#define OFF_SC2 0
#define OFF_SN5 1024
#define OFF_SXF 2048                     // 256 x 34 f32 = 34816
#define OFF_SCF (OFF_SXF + 34816)        // 256 x 33 f32 = 33792
#define OFF_RQ  (OFF_SCF + 33792)        // 256 x 8 f32  = 8192
#define OFF_RI  (OFF_RQ + 8192)          // 256 x 8 i32  = 8192
#define OFF_B1H (OFF_RI + 8192)          // 256 x 40 bf16 = 20480
#define OFF_B1L (OFF_B1H + 20480)
#define OFF_B2H (OFF_B1L + 20480)        // 32 x 264 fp16 = 16896
#define SMEM_TOTAL (OFF_B2H + 16896)     // 144896

__device__ __forceinline__ uint32_t cvta_s(const void* p) {
    uint32_t a;
    asm("{ .reg .u64 t; cvta.to.shared.u64 t, %1; cvt.u32.u64 %0, t; }" : "=r"(a) : "l"(p));
    return a;
}
__device__ __forceinline__ uint32_t packbf(float lo, float hi) {
    uint32_t r;
    asm("cvt.rn.bf16x2.f32 %0, %1, %2;" : "=r"(r) : "f"(hi), "f"(lo));
    return r;
}
__device__ __forceinline__ uint32_t packh(float lo, float hi) {
    __half2 h = __floats2half2_rn(lo, hi);
    return *(uint32_t*)&h;
}
__device__ __forceinline__ void ldsm4(uint32_t a, uint32_t& r0, uint32_t& r1, uint32_t& r2, uint32_t& r3) {
    asm volatile("ldmatrix.sync.aligned.m8n8.x4.shared.b16 {%0,%1,%2,%3}, [%4];"
                 : "=r"(r0), "=r"(r1), "=r"(r2), "=r"(r3) : "r"(a));
}
__device__ __forceinline__ void mma16816(float* d, const uint32_t* a, uint32_t b0, uint32_t b1) {
    asm volatile("mma.sync.aligned.m16n8k16.row.col.f32.bf16.bf16.f32 "
                 "{%0,%1,%2,%3}, {%4,%5,%6,%7}, {%8,%9}, {%0,%1,%2,%3};"
                 : "+f"(d[0]), "+f"(d[1]), "+f"(d[2]), "+f"(d[3])
                 : "r"(a[0]), "r"(a[1]), "r"(a[2]), "r"(a[3]), "r"(b0), "r"(b1));
}
__device__ __forceinline__ void mma16816h(float* d, const uint32_t* a, uint32_t b0, uint32_t b1) {
    asm volatile("mma.sync.aligned.m16n8k16.row.col.f32.f16.f16.f32 "
                 "{%0,%1,%2,%3}, {%4,%5,%6,%7}, {%8,%9}, {%0,%1,%2,%3};"
                 : "+f"(d[0]), "+f"(d[1]), "+f"(d[2]), "+f"(d[3])
                 : "r"(a[0]), "r"(a[1]), "r"(a[2]), "r"(a[3]), "r"(b0), "r"(b1));
}

// Exact tree sum of squares (reference bit chain — frozen)
__device__ __forceinline__ float tree_sumsq32(const float* v) {
    float s[32];
    #pragma unroll
    for (int i = 0; i < 32; ++i) s[i] = __fmul_rn(v[i], v[i]);
    #pragma unroll
    for (int st = 16; st >= 1; st >>= 1) {
        #pragma unroll
        for (int i = 0; i < st; ++i) s[i] = __fadd_rn(s[i], s[i + st]);
    }
    return s[0];
}

#define INS2(qv, wv, Q, I) do { \
    if ((qv) > Q[1]) { \
        if ((qv) > Q[0]) { Q[1]=Q[0]; I[1]=I[0]; Q[0]=(qv); I[0]=(wv); } \
        else             { Q[1]=(qv); I[1]=(wv); } \
    } } while (0)

__global__ void __launch_bounds__(THREADS, 1)
softpq_mma(const float* __restrict__ x, const float* __restrict__ C, float* __restrict__ out)
{
    extern __shared__ char sm[];
    float* sc2 = (float*)(sm + OFF_SC2);
    float* sn5 = (float*)(sm + OFF_SN5);
    float* sXf = (float*)(sm + OFF_SXF);
    float* sCf = (float*)(sm + OFF_SCF);
    float* rqA = (float*)(sm + OFF_RQ);
    int*   riA = (int*)(sm + OFF_RI);
    __nv_bfloat16* b1h = (__nv_bfloat16*)(sm + OFF_B1H);
    __nv_bfloat16* b1l = (__nv_bfloat16*)(sm + OFF_B1L);
    __half*        b2h = (__half*)(sm + OFF_B2H);

    const uint32_t sb1h = cvta_s(sm + OFF_B1H), sb1l = cvta_s(sm + OFF_B1L);
    const uint32_t sb2h = cvta_s(sm + OFF_B2H);

    const int tid = threadIdx.x, wid = tid >> 5, lid = tid & 31;
    const int g = lid >> 2, tig = lid & 3;
    const int lq = lid >> 3, lr = lid & 7;
    const int rowbase = blockIdx.x * RPC;

    #pragma unroll 1
    for (int book = 0; book < NB; ++book) {
        // ================= Phase A: stage smem =================
        if (tid < 256) {
            const int w = tid;
            float cv[32];
            const float4* cs = (const float4*)(C + (size_t)w * DDIM + book * LW);
            #pragma unroll
            for (int j = 0; j < 8; ++j) {
                float4 v = cs[j];
                cv[4*j+0] = v.x; cv[4*j+1] = v.y; cv[4*j+2] = v.z; cv[4*j+3] = v.w;
            }
            float c2 = tree_sumsq32(cv);
            sc2[w] = c2;
            sn5[w] = -TAUQ * c2;
            #pragma unroll
            for (int k = 0; k < 32; ++k) {
                float v = cv[k];
                sCf[w * CFS + k] = v;
                __nv_bfloat16 h = __float2bfloat16(v);
                __nv_bfloat16 l = __float2bfloat16(v - __bfloat162float(h));
                b1h[w * B1S + k] = h;  b1l[w * B1S + k] = l;
                b2h[k * B2S + w] = __float2half(v);
            }
        } else {
            const int row = tid - 256;
            const float4* xs = (const float4*)(x + (size_t)(rowbase + row) * DDIM + book * LW);
            #pragma unroll
            for (int j = 0; j < 8; ++j) {
                float4 v = xs[j];
                float* d = &sXf[row * XFS + 4 * j];
                d[0] = v.x; d[1] = v.y; d[2] = v.z; d[3] = v.w;
            }
        }
        __syncthreads();

        // ================= Build A1 fragments (X, split bf16) ===============
        uint32_t a1h[2][4], a1l[2][4];
        {
            const int r0 = wid * 16 + g;
            #pragma unroll
            for (int c = 0; c < 2; ++c) {
                const int d0 = c * 16 + 2 * tig;
                #pragma unroll
                for (int rr = 0; rr < 2; ++rr) {
                    const float* xr = &sXf[(r0 + rr * 8) * XFS];
                    float v0 = xr[d0], v1 = xr[d0+1], v8 = xr[d0+8], v9 = xr[d0+9];
                    __nv_bfloat16 h0 = __float2bfloat16(v0), h1 = __float2bfloat16(v1);
                    __nv_bfloat16 h8 = __float2bfloat16(v8), h9 = __float2bfloat16(v9);
                    float l0 = v0 - __bfloat162float(h0), l1 = v1 - __bfloat162float(h1);
                    float l8 = v8 - __bfloat162float(h8), l9 = v9 - __bfloat162float(h9);
                    a1h[c][rr]     = packbf(__bfloat162float(h0), __bfloat162float(h1));
                    a1h[c][2 + rr] = packbf(__bfloat162float(h8), __bfloat162float(h9));
                    a1l[c][rr]     = packbf(l0, l1);
                    a1l[c][2 + rr] = packbf(l8, l9);
                }
            }
        }

        float d2[4][4];
        #pragma unroll
        for (int t = 0; t < 4; ++t)
            #pragma unroll
            for (int e = 0; e < 4; ++e) d2[t][e] = 0.f;

        float tq0[2] = {-3.4e38f, -3.4e38f}, tq1[2] = {-3.4e38f, -3.4e38f};
        int   ti0[2] = {-1, -1},             ti1[2] = {-1, -1};
        float ss0 = 0.f, ss1 = 0.f;

        // ================= Main loop: 16 codeword chunks ====================
        #pragma unroll 1
        for (int i = 0; i < 16; ++i) {
            float dt0[4] = {0.f, 0.f, 0.f, 0.f}, dt1[4] = {0.f, 0.f, 0.f, 0.f};
            #pragma unroll
            for (int kc = 0; kc < 2; ++kc) {
                uint32_t b4h[4], b4l[4];
                uint32_t base = (uint32_t)((16 * i + (lq >> 1) * 8 + lr) * (B1S * 2)
                                           + (lq & 1) * 16 + kc * 32);
                ldsm4(sb1h + base, b4h[0], b4h[1], b4h[2], b4h[3]);
                ldsm4(sb1l + base, b4l[0], b4l[1], b4l[2], b4l[3]);
                mma16816(dt0, a1h[kc], b4h[0], b4h[1]);
                mma16816(dt0, a1h[kc], b4l[0], b4l[1]);
                mma16816(dt0, a1l[kc], b4h[0], b4h[1]);
                mma16816(dt1, a1h[kc], b4h[2], b4h[3]);
                mma16816(dt1, a1h[kc], b4l[2], b4l[3]);
                mma16816(dt1, a1l[kc], b4h[2], b4h[3]);
            }

            // --- epilogue: q, top2, exp, fp16 P ---
            const int w0 = 16 * i + 2 * tig;
            float2 pa = *(const float2*)&sn5[w0];
            float2 pb = *(const float2*)&sn5[w0 + 8];
            float qa0 = fmaf(10.f, dt0[0], pa.x), qa1 = fmaf(10.f, dt0[1], pa.y);
            float qb0 = fmaf(10.f, dt1[0], pb.x), qb1 = fmaf(10.f, dt1[1], pb.y);
            float qc0 = fmaf(10.f, dt0[2], pa.x), qc1 = fmaf(10.f, dt0[3], pa.y);
            float qd0 = fmaf(10.f, dt1[2], pb.x), qd1 = fmaf(10.f, dt1[3], pb.y);
            INS2(qa0, w0,     tq0, ti0); INS2(qa1, w0 + 1, tq0, ti0);
            INS2(qb0, w0 + 8, tq0, ti0); INS2(qb1, w0 + 9, tq0, ti0);
            INS2(qc0, w0,     tq1, ti1); INS2(qc1, w0 + 1, tq1, ti1);
            INS2(qd0, w0 + 8, tq1, ti1); INS2(qd1, w0 + 9, tq1, ti1);
            float pa0 = __expf(qa0), pa1 = __expf(qa1), pb0 = __expf(qb0), pb1 = __expf(qb1);
            float pc0 = __expf(qc0), pc1 = __expf(qc1), pd0 = __expf(qd0), pd1 = __expf(qd1);
            ss0 += (pa0 + pa1) + (pb0 + pb1);
            ss1 += (pc0 + pc1) + (pd0 + pd1);

            // P fragments in fp16 (single pass, fp32 accumulate)
            uint32_t a2[4];
            a2[0] = packh(pa0, pa1);
            a2[1] = packh(pc0, pc1);
            a2[2] = packh(pb0, pb1);
            a2[3] = packh(pd0, pd1);

            // --- GEMM2 online accumulation (fp16 single pass) ---
            #pragma unroll
            for (int hf2 = 0; hf2 < 2; ++hf2) {
                uint32_t c4[4];
                uint32_t o = (uint32_t)((hf2 * 16 + (lq >> 1) * 8 + lr) * (B2S * 2)
                                        + (16 * i + (lq & 1) * 8) * 2);
                ldsm4(sb2h + o, c4[0], c4[1], c4[2], c4[3]);
                mma16816h(d2[hf2 * 2 + 0], a2, c4[0], c4[1]);
                mma16816h(d2[hf2 * 2 + 1], a2, c4[2], c4[3]);
            }
        }

        // ================= reduce ssum across quad, store Z =================
        ss0 += __shfl_xor_sync(0xffffffffu, ss0, 1);
        ss0 += __shfl_xor_sync(0xffffffffu, ss0, 2);
        ss1 += __shfl_xor_sync(0xffffffffu, ss1, 1);
        ss1 += __shfl_xor_sync(0xffffffffu, ss1, 2);
        const float inv0 = 1.f / ss0, inv1 = 1.f / ss1;

        {
            const int r0 = rowbase + wid * 16 + g;
            #pragma unroll
            for (int t = 0; t < 4; ++t) {
                size_t o = (size_t)r0 * DDIM + book * LW + 8 * t + 2 * tig;
                *(float2*)&out[o]            = make_float2(d2[t][0] * inv0, d2[t][1] * inv0);
                *(float2*)&out[o + 8 * DDIM] = make_float2(d2[t][2] * inv1, d2[t][3] * inv1);
            }
        }

        // ================= stage candidates, recheck, idx ===================
        {
            const int lr0 = wid * 16 + g;
            #pragma unroll
            for (int c = 0; c < 2; ++c) {
                rqA[lr0 * 8 + tig * 2 + c] = tq0[c];
                riA[lr0 * 8 + tig * 2 + c] = ti0[c];
                rqA[(lr0 + 8) * 8 + tig * 2 + c] = tq1[c];
                riA[(lr0 + 8) * 8 + tig * 2 + c] = ti1[c];
            }
        }
        __syncthreads();

        if (tid < 256) {
            const int row = tid;
            float qs[8]; int is[8];
            #pragma unroll
            for (int c = 0; c < 8; ++c) { qs[c] = rqA[row * 8 + c]; is[c] = riA[row * 8 + c]; }
            float qmax = qs[0];
            #pragma unroll
            for (int c = 1; c < 8; ++c) qmax = fmaxf(qmax, qs[c]);

            float xv[32];
            #pragma unroll
            for (int k = 0; k < 32; ++k) xv[k] = sXf[row * XFS + k];
            const float X2 = tree_sumsq32(xv);

            float bestKey = -3.4e38f; int bestW = NW;
            #pragma unroll 1
            for (int c = 0; c < 8; ++c) {
                int w = is[c];
                if (w < 0 || qs[c] < qmax - QMARGIN) continue;
                const float* cw = sCf + w * CFS;
                float de = 0.f;
                #pragma unroll
                for (int k = 0; k < 32; ++k) de = __fmaf_rn(xv[k], cw[k], de);
                float t    = __fadd_rn(X2, sc2[w]);
                float dist = __fmaf_rn(-2.f, de, t);
                float key  = __fmul_rn(-TAUQ, dist);
                if (key > bestKey || (key == bestKey && w < bestW)) { bestKey = key; bestW = w; }
            }
            out[(size_t)Z_ELEMS + (size_t)(rowbase + row) * NB + book] = (float)bestW;
        }
        __syncthreads();
    }
}

__global__ void copy_c_kernel(const float* __restrict__ C, float* __restrict__ out)
{
    int i = blockIdx.x * blockDim.x + threadIdx.x;
    if (i < C_ELEMS) out[(size_t)Z_ELEMS + IDX_ELEMS + i] = C[i];
}

extern "C" void kernel_launch(void* const* d_in, const int* in_sizes, int n_in,
                              void* d_out, int out_size)
{
    const float* x = (const float*)d_in[0];
    const float* C = (const float*)d_in[1];
    float* out = (float*)d_out;

    cudaFuncSetAttribute(softpq_mma, cudaFuncAttributeMaxDynamicSharedMemorySize, SMEM_TOTAL);
    // copy_c first so ncu's skip-count lands on the main kernel
    copy_c_kernel<<<(C_ELEMS + 255) / 256, 256>>>(C, out);
    softpq_mma<<<NROWS / RPC, THREADS, SMEM_TOTAL>>>(x, C, out);
}